// round 2
// baseline (speedup 1.0000x reference)
#include <cuda_runtime.h>
#include <math.h>

#define CC 256
#define TT 4096
#define BB 8
#define BC (BB*CC)
#define ALPHA 0.8187307530779818f
#define ONE_M_ALPHA 0.1812692469220182f
#define A16 0.04076220397836621f   /* ALPHA^16 = exp(-3.2) */
#define XSW (TT+8)

// Precomputed effective filters: drive[b,c,t]*(1-alpha) =
//   g_be[c] + sum_{m<3} sum_{tap<9} g_E[c][m][tap] * x[b, g_idx[c][m], t+tap-4]
__device__ float g_E[CC][3][9];
__device__ int   g_idx[CC][3];
__device__ float g_be[CC];

__global__ void prep_kernel(const float* __restrict__ w3, const float* __restrict__ b3,
                            const float* __restrict__ w5, const float* __restrict__ b5,
                            const float* __restrict__ w9, const float* __restrict__ b9,
                            const float* __restrict__ wred, const float* __restrict__ bred) {
    int c = threadIdx.x;
    if (c >= CC) return;
    float E[3][9];
    #pragma unroll
    for (int m = 0; m < 3; m++)
        #pragma unroll
        for (int t = 0; t < 9; t++) E[m][t] = 0.f;
    int idx[3]; int nm = 0;
    float be = bred[c];
    for (int k = 0; k < 18; k++) {
        int j = 18 * c + k;
        const float* w; const float* bb; int pc, K;
        if (j < 6 * CC)       { w = w3; bb = b3; pc = j;          K = 3; }
        else if (j < 12 * CC) { w = w5; bb = b5; pc = j - 6*CC;   K = 5; }
        else                  { w = w9; bb = b9; pc = j - 12*CC;  K = 9; }
        int pad = (K - 1) / 2;
        int xch = pc / 6;
        int m = -1;
        for (int t2 = 0; t2 < nm; t2++) if (idx[t2] == xch) m = t2;
        if (m < 0) { m = nm; idx[nm++] = xch; }
        float wr = wred[c * 18 + k];
        be += wr * bb[pc];
        for (int u = 0; u < K; u++) E[m][4 + u - pad] += wr * w[pc * K + u];
    }
    for (int m = nm; m < 3; m++) idx[m] = 0;   // E already zero there
    for (int m = 0; m < 3; m++) {
        g_idx[c][m] = idx[m];
        for (int t = 0; t < 9; t++) g_E[c][m][t] = E[m][t] * ONE_M_ALPHA;
    }
    g_be[c] = be * ONE_M_ALPHA;
}

// One block per (b, c). 256 threads, 16 timesteps/thread.
// out layout: [0, BC) pred (filled later), [BC, 2BC) true_latency, [2BC, 3BC) act.
__global__ void __launch_bounds__(256) lif_kernel(const float* __restrict__ x,
                                                  const float* __restrict__ lat_scale,
                                                  float* __restrict__ out) {
    extern __shared__ float smem[];
    float* xs = smem;                 // 3 * XSW
    float* sa = xs + 3 * XSW;         // 256
    float* sb = sa + 256;             // 256
    float* sE = sb + 256;             // 27
    __shared__ int s_first;

    int tid = threadIdx.x;
    int bc  = blockIdx.x;
    int b   = bc >> 8;
    int c   = bc & 255;

    if (tid < 27) sE[tid] = ((const float*)g_E)[c * 27 + tid];
    if (tid == 0) s_first = TT;

    // stage 3 input rows (with 4-wide zero halo each side)
    #pragma unroll
    for (int m = 0; m < 3; m++) {
        const float4* row = (const float4*)(x + ((size_t)(b * CC + g_idx[c][m])) * TT);
        float4* dst = (float4*)(xs + m * XSW + 4);
        for (int i = tid; i < TT / 4; i += 256) dst[i] = row[i];
    }
    if (tid < 4) {
        #pragma unroll
        for (int m = 0; m < 3; m++) {
            xs[m * XSW + tid] = 0.f;
            xs[m * XSW + 4 + TT + tid] = 0.f;
        }
    }
    __syncthreads();

    int t0 = tid * 16;
    float be = g_be[c];
    float u[16];
    #pragma unroll
    for (int jj = 0; jj < 16; jj++) u[jj] = be;

    #pragma unroll
    for (int m = 0; m < 3; m++) {
        const float* xr = xs + m * XSW + t0;   // xr[i] == x[t0 + i - 4]
        float w[24];
        #pragma unroll
        for (int i = 0; i < 24; i++) w[i] = xr[i];
        float e[9];
        #pragma unroll
        for (int t = 0; t < 9; t++) e[t] = sE[m * 9 + t];
        #pragma unroll
        for (int jj = 0; jj < 16; jj++) {
            #pragma unroll
            for (int tap = 0; tap < 9; tap++)
                u[jj] = fmaf(e[tap], w[jj + tap], u[jj]);
        }
    }

    // per-segment (a, b): segment maps V -> A16*V + bacc
    float bacc = 0.f;
    #pragma unroll
    for (int jj = 0; jj < 16; jj++) bacc = fmaf(ALPHA, bacc, u[jj]);
    sa[tid] = A16;
    sb[tid] = bacc;
    __syncthreads();

    // Hillis-Steele inclusive scan of (a, b) composition
    for (int s = 1; s < 256; s <<= 1) {
        float a2 = sa[tid], b2 = sb[tid];
        float a1 = 1.f, b1 = 0.f;
        if (tid >= s) { a1 = sa[tid - s]; b1 = sb[tid - s]; }
        __syncthreads();
        if (tid >= s) { sa[tid] = a1 * a2; sb[tid] = fmaf(a2, b1, b2); }
        __syncthreads();
    }

    float V = (tid == 0) ? 0.f : sb[tid - 1];
    int ft = 0x7fffffff;
    #pragma unroll
    for (int jj = 0; jj < 16; jj++) {
        V = fmaf(ALPHA, V, u[jj]);
        if (V >= 1.0f && ft == 0x7fffffff) ft = t0 + jj;
    }
    if (ft != 0x7fffffff) atomicMin(&s_first, ft);
    __syncthreads();

    if (tid == 0) {
        float tl = (float)s_first;                 // T (=4096) if never fired
        out[BC + bc] = tl;
        float scale = fmaxf(lat_scale[0], 0.001f);
        out[2 * BC + bc] = expf(-tl / scale);
    }
}

// act (B,C) -> gated mix -> MLP -> softplus clamp. One block per batch row.
__global__ void __launch_bounds__(256) mlp_kernel(const float* __restrict__ OG,
                                                  const float* __restrict__ bias,
                                                  const float* __restrict__ W1,
                                                  const float* __restrict__ b1,
                                                  const float* __restrict__ W2,
                                                  const float* __restrict__ b2,
                                                  float* __restrict__ out) {
    __shared__ float sact[256], smix[256], sh[128];
    int b = blockIdx.x, i = threadIdx.x;
    sact[i] = out[2 * BC + b * CC + i];
    __syncthreads();

    float acc = bias[i];
    #pragma unroll 8
    for (int j = 0; j < 256; j++) acc = fmaf(sact[j], OG[i * 256 + j], acc);
    smix[i] = acc;
    __syncthreads();

    if (i < 128) {
        float h = b1[i];
        #pragma unroll 8
        for (int j = 0; j < 256; j++) h = fmaf(smix[j], W1[j * 128 + i], h);
        sh[i] = fmaxf(h, 0.f);
    }
    __syncthreads();

    float r = b2[i];
    #pragma unroll 8
    for (int k = 0; k < 128; k++) r = fmaf(sh[k], W2[k * 256 + i], r);
    float sp = (r > 20.f) ? r : log1pf(expf(r));
    out[b * CC + i] = fminf(sp, 4096.0f);
}

extern "C" void kernel_launch(void* const* d_in, const int* in_sizes, int n_in,
                              void* d_out, int out_size) {
    const float* x    = (const float*)d_in[0];
    const float* w3   = (const float*)d_in[1];
    const float* b3   = (const float*)d_in[2];
    const float* w5   = (const float*)d_in[3];
    const float* b5   = (const float*)d_in[4];
    const float* w9   = (const float*)d_in[5];
    const float* b9   = (const float*)d_in[6];
    const float* wred = (const float*)d_in[7];
    const float* bred = (const float*)d_in[8];
    const float* ls   = (const float*)d_in[9];
    const float* og   = (const float*)d_in[10];
    const float* bias = (const float*)d_in[11];
    const float* W1   = (const float*)d_in[12];
    const float* b1   = (const float*)d_in[13];
    const float* W2   = (const float*)d_in[14];
    const float* b2   = (const float*)d_in[15];
    float* out = (float*)d_out;

    size_t smem = (size_t)(3 * XSW + 256 + 256 + 32) * sizeof(float);
    cudaFuncSetAttribute(lif_kernel, cudaFuncAttributeMaxDynamicSharedMemorySize, (int)smem);

    prep_kernel<<<1, 256>>>(w3, b3, w5, b5, w9, b9, wred, bred);
    lif_kernel<<<BC, 256, smem>>>(x, ls, out);
    mlp_kernel<<<BB, 256>>>(og, bias, W1, b1, W2, b2, out);
}

// round 3
// speedup vs baseline: 1.1792x; 1.1792x over previous
#include <cuda_runtime.h>
#include <math.h>

#define CC 256
#define TT 4096
#define BB 8
#define BC (BB*CC)
#define ALPHA 0.8187307530779818f
#define ONE_M_ALPHA 0.1812692469220182f
#define A16 0.04076220397836621f   /* ALPHA^16 */
#define XSW (TT+8)                 /* 4104 floats; 16416 bytes -> keeps float4 alignment */

// One block per (b, c). 256 threads, 16 timesteps/thread.
// out layout: [0, BC) pred (filled by mlp), [BC, 2BC) true_latency, [2BC, 3BC) act.
__global__ void __launch_bounds__(256) lif_kernel(
        const float* __restrict__ x,
        const float* __restrict__ w3, const float* __restrict__ b3,
        const float* __restrict__ w5, const float* __restrict__ b5,
        const float* __restrict__ w9, const float* __restrict__ b9,
        const float* __restrict__ wred, const float* __restrict__ bred,
        const float* __restrict__ lat_scale,
        float* __restrict__ out) {
    extern __shared__ float xs[];        // 3 * XSW
    __shared__ float sE[27];
    __shared__ float sbe;
    __shared__ float swa[8], swb[8];
    __shared__ int s_first;

    int tid  = threadIdx.x;
    int lane = tid & 31;
    int wrp  = tid >> 5;
    int bc = blockIdx.x;
    int b  = bc >> 8;
    int c  = bc & 255;

    if (tid < 27)  sE[tid] = 0.f;
    if (tid == 27) sbe = bred[c];
    if (tid == 28) s_first = TT;
    __syncthreads();

    // ---- stage 3 input rows (channels (3c+m) & 255), 4-wide zero halo ----
    #pragma unroll
    for (int m = 0; m < 3; m++) {
        int xch = (3 * c + m) & 255;
        const float4* row = (const float4*)(x + ((size_t)(b * CC + xch)) * TT);
        float4* dst = (float4*)(xs + m * XSW + 4);
        for (int i = tid; i < TT / 4; i += 256) dst[i] = row[i];
    }
    if (tid < 4) {
        #pragma unroll
        for (int m = 0; m < 3; m++) {
            xs[m * XSW + tid] = 0.f;
            xs[m * XSW + 4 + TT + tid] = 0.f;
        }
    }

    // ---- in-block effective-filter computation (overlaps with staging) ----
    if (tid < 18) {
        int k = tid, m = k / 6, j = 18 * c + k;
        const float* w; const float* bb; int pc, K;
        if (j < 6 * CC)       { w = w3; bb = b3; pc = j;          K = 3; }
        else if (j < 12 * CC) { w = w5; bb = b5; pc = j - 6*CC;   K = 5; }
        else                  { w = w9; bb = b9; pc = j - 12*CC;  K = 9; }
        int pad = (K - 1) / 2;
        float wr = wred[c * 18 + k];
        atomicAdd(&sbe, wr * bb[pc]);
        for (int u2 = 0; u2 < K; u2++)
            atomicAdd(&sE[m * 9 + 4 + u2 - pad], wr * w[pc * K + u2]);
    }
    __syncthreads();

    // ---- per-thread 16-step segment: u[jj] = (1-alpha)*drive[t0+jj] ----
    int t0 = tid * 16;
    float be = sbe * ONE_M_ALPHA;
    float u[16];
    #pragma unroll
    for (int jj = 0; jj < 16; jj++) u[jj] = be;

    #pragma unroll
    for (int m = 0; m < 3; m++) {
        const float4* xr4 = (const float4*)(xs + m * XSW + t0);  // [i] == x[t0+i-4]
        float w[24];
        #pragma unroll
        for (int i = 0; i < 6; i++) {
            float4 v = xr4[i];
            w[4*i] = v.x; w[4*i+1] = v.y; w[4*i+2] = v.z; w[4*i+3] = v.w;
        }
        float e[9];
        #pragma unroll
        for (int t = 0; t < 9; t++) e[t] = sE[m * 9 + t] * ONE_M_ALPHA;
        #pragma unroll
        for (int jj = 0; jj < 16; jj++) {
            #pragma unroll
            for (int tap = 0; tap < 9; tap++)
                u[jj] = fmaf(e[tap], w[jj + tap], u[jj]);
        }
    }

    // ---- segment transform V -> A16*V + bacc ----
    float bacc = 0.f;
    #pragma unroll
    for (int jj = 0; jj < 16; jj++) bacc = fmaf(ALPHA, bacc, u[jj]);

    // warp-inclusive scan of (a, b) composition via shuffles
    float a = A16, bs = bacc;
    #pragma unroll
    for (int s = 1; s < 32; s <<= 1) {
        float ao = __shfl_up_sync(0xffffffffu, a, s);
        float bo = __shfl_up_sync(0xffffffffu, bs, s);
        if (lane >= s) { bs = fmaf(a, bo, bs); a *= ao; }
    }
    if (lane == 31) { swa[wrp] = a; swb[wrp] = bs; }
    __syncthreads();

    // warp-exclusive prefix (applied to V=0): pb = V at start of this warp
    float pb = 0.f;
    for (int ww = 0; ww < wrp; ww++) pb = fmaf(swa[ww], pb, swb[ww]);

    // lane-exclusive transform
    float ae = __shfl_up_sync(0xffffffffu, a, 1);
    float bse = __shfl_up_sync(0xffffffffu, bs, 1);
    if (lane == 0) { ae = 1.f; bse = 0.f; }
    float V = fmaf(ae, pb, bse);   // V at start of this thread's segment

    int ft = 0x7fffffff;
    #pragma unroll
    for (int jj = 0; jj < 16; jj++) {
        V = fmaf(ALPHA, V, u[jj]);
        if (V >= 1.0f && ft == 0x7fffffff) ft = t0 + jj;
    }
    if (ft != 0x7fffffff) atomicMin(&s_first, ft);
    __syncthreads();

    if (tid == 0) {
        float tl = (float)s_first;                 // T if never fired
        out[BC + bc] = tl;
        float scale = fmaxf(lat_scale[0], 0.001f);
        out[2 * BC + bc] = expf(-tl / scale);
    }
}

// act (B,C) -> gated mix -> MLP -> softplus clamp. One block per batch row.
__global__ void __launch_bounds__(256) mlp_kernel(const float* __restrict__ OG,
                                                  const float* __restrict__ bias,
                                                  const float* __restrict__ W1,
                                                  const float* __restrict__ b1,
                                                  const float* __restrict__ W2,
                                                  const float* __restrict__ b2,
                                                  float* __restrict__ out) {
    __shared__ float sact[256], smix[256], sh[128];
    int b = blockIdx.x, i = threadIdx.x;
    sact[i] = out[2 * BC + b * CC + i];
    __syncthreads();

    float acc = bias[i];
    #pragma unroll 8
    for (int j = 0; j < 256; j++) acc = fmaf(sact[j], OG[i * 256 + j], acc);
    smix[i] = acc;
    __syncthreads();

    if (i < 128) {
        float h = b1[i];
        #pragma unroll 8
        for (int j = 0; j < 256; j++) h = fmaf(smix[j], W1[j * 128 + i], h);
        sh[i] = fmaxf(h, 0.f);
    }
    __syncthreads();

    float r = b2[i];
    #pragma unroll 8
    for (int k = 0; k < 128; k++) r = fmaf(sh[k], W2[k * 256 + i], r);
    float sp = (r > 20.f) ? r : log1pf(expf(r));
    out[b * CC + i] = fminf(sp, 4096.0f);
}

extern "C" void kernel_launch(void* const* d_in, const int* in_sizes, int n_in,
                              void* d_out, int out_size) {
    const float* x    = (const float*)d_in[0];
    const float* w3   = (const float*)d_in[1];
    const float* b3   = (const float*)d_in[2];
    const float* w5   = (const float*)d_in[3];
    const float* b5   = (const float*)d_in[4];
    const float* w9   = (const float*)d_in[5];
    const float* b9   = (const float*)d_in[6];
    const float* wred = (const float*)d_in[7];
    const float* bred = (const float*)d_in[8];
    const float* ls   = (const float*)d_in[9];
    const float* og   = (const float*)d_in[10];
    const float* bias = (const float*)d_in[11];
    const float* W1   = (const float*)d_in[12];
    const float* b1   = (const float*)d_in[13];
    const float* W2   = (const float*)d_in[14];
    const float* b2   = (const float*)d_in[15];
    float* out = (float*)d_out;

    size_t smem = (size_t)(3 * XSW) * sizeof(float);
    cudaFuncSetAttribute(lif_kernel, cudaFuncAttributeMaxDynamicSharedMemorySize, (int)smem);

    lif_kernel<<<BC, 256, smem>>>(x, w3, b3, w5, b5, w9, b9, wred, bred, ls, out);
    mlp_kernel<<<BB, 256>>>(og, bias, W1, b1, W2, b2, out);
}

// round 4
// speedup vs baseline: 1.8053x; 1.5310x over previous
#include <cuda_runtime.h>
#include <math.h>

#define CC 256
#define TT 4096
#define BB 8
#define BC (BB*CC)
#define ALPHA 0.8187307530779818f
#define ONE_M_ALPHA 0.1812692469220182f
#define A16 0.04076220397836621f   /* ALPHA^16 */
#define XSW (TT+8)                 /* keeps float4 alignment */

typedef unsigned long long ull;

// Effective-filter coefficients, duplicated-pair packed: (e,e) as f32x2, already * (1-alpha)
__device__ ull   g_E2[CC][3][9];
__device__ float g_beP[CC][3];     // bias partials * (1-alpha); m=0 slot includes bred
__device__ float g_mix[BC];
__device__ float g_hp[4 * BB * 128];

__device__ __forceinline__ ull pk2(float lo, float hi) {
    ull r; asm("mov.b64 %0, {%1, %2};" : "=l"(r) : "f"(lo), "f"(hi)); return r;
}
__device__ __forceinline__ void upk2(float& lo, float& hi, ull v) {
    asm("mov.b64 {%0, %1}, %2;" : "=f"(lo), "=f"(hi) : "l"(v));
}
__device__ __forceinline__ void fma2(ull& d, ull a, ull b) {
    asm("fma.rn.f32x2 %0, %1, %2, %0;" : "+l"(d) : "l"(a), "l"(b));
}

// ---------------- prep: thread = (c, m); 6 consecutive cat-channels each ----------------
__global__ void prep_kernel(const float* __restrict__ w3, const float* __restrict__ b3,
                            const float* __restrict__ w5, const float* __restrict__ b5,
                            const float* __restrict__ w9, const float* __restrict__ b9,
                            const float* __restrict__ wred, const float* __restrict__ bred) {
    int c = threadIdx.x;           // 0..255
    int m = blockIdx.x;            // 0..2
    int j0 = 18 * c + 6 * m;       // 6-aligned run, never straddles bucket boundary
    const float* w; const float* bb; int K, pc0;
    if (j0 < 6 * CC)       { w = w3; bb = b3; K = 3; pc0 = j0; }
    else if (j0 < 12 * CC) { w = w5; bb = b5; K = 5; pc0 = j0 - 6 * CC; }
    else                   { w = w9; bb = b9; K = 9; pc0 = j0 - 12 * CC; }
    int pad = (K - 1) / 2;

    float E[9];
    #pragma unroll
    for (int t = 0; t < 9; t++) E[t] = 0.f;
    float be = (m == 0) ? bred[c] : 0.f;

    for (int r = 0; r < 6; r++) {
        float wr = wred[c * 18 + 6 * m + r];
        be += wr * bb[pc0 + r];
        for (int u = 0; u < K; u++)
            E[4 + u - pad] += wr * w[(pc0 + r) * K + u];
    }
    #pragma unroll
    for (int t = 0; t < 9; t++) {
        float e = E[t] * ONE_M_ALPHA;
        g_E2[c][m][t] = pk2(e, e);
    }
    g_beP[c][m] = be * ONE_M_ALPHA;
}

// ---------------- lif: one block per (b, c); 16 timesteps/thread ----------------
// out layout: [0,BC) pred (by k_pred), [BC,2BC) true_latency, [2BC,3BC) act.
__global__ void __launch_bounds__(256, 2) lif_kernel(const float* __restrict__ x,
                                                     const float* __restrict__ lat_scale,
                                                     float* __restrict__ out) {
    extern __shared__ float xs[];            // 3 * XSW
    __shared__ ull sE2[27];
    __shared__ float swa[8], swb[8];
    __shared__ int s_first;

    int tid  = threadIdx.x;
    int lane = tid & 31;
    int wrp  = tid >> 5;
    int bc = blockIdx.x;
    int b  = bc >> 8;
    int c  = bc & 255;

    if (tid < 27) sE2[tid] = ((const ull*)g_E2)[c * 27 + tid];
    if (tid == 28) s_first = TT;

    // stage 3 input rows (channels (3c+m) mod 256), 4-wide zero halo
    #pragma unroll
    for (int m = 0; m < 3; m++) {
        int xch = (3 * c + m) & 255;
        const float4* row = (const float4*)(x + ((size_t)(b * CC + xch)) * TT);
        float4* dst = (float4*)(xs + m * XSW + 4);
        for (int i = tid; i < TT / 4; i += 256) dst[i] = row[i];
    }
    if (tid < 4) {
        #pragma unroll
        for (int m = 0; m < 3; m++) {
            xs[m * XSW + tid] = 0.f;
            xs[m * XSW + 4 + TT + tid] = 0.f;
        }
    }
    __syncthreads();

    int t0 = tid * 16;
    float be = g_beP[c][0] + g_beP[c][1] + g_beP[c][2];

    ull U[8];
    ull be2 = pk2(be, be);
    #pragma unroll
    for (int p = 0; p < 8; p++) U[p] = be2;

    #pragma unroll
    for (int m = 0; m < 3; m++) {
        const float4* xr4 = (const float4*)(xs + m * XSW + t0);  // [i] == x[t0+i-4]
        float w[24];
        #pragma unroll
        for (int i = 0; i < 6; i++) {
            float4 v = xr4[i];
            w[4*i] = v.x; w[4*i+1] = v.y; w[4*i+2] = v.z; w[4*i+3] = v.w;
        }
        ull p0[12], p1[11];
        #pragma unroll
        for (int k = 0; k < 12; k++) p0[k] = pk2(w[2*k], w[2*k+1]);
        #pragma unroll
        for (int k = 0; k < 11; k++) p1[k] = pk2(w[2*k+1], w[2*k+2]);

        #pragma unroll
        for (int t = 0; t < 9; t++) {
            ull e2 = sE2[m * 9 + t];
            if ((t & 1) == 0) {
                #pragma unroll
                for (int p = 0; p < 8; p++) fma2(U[p], e2, p0[p + (t >> 1)]);
            } else {
                #pragma unroll
                for (int p = 0; p < 8; p++) fma2(U[p], e2, p1[p + (t >> 1)]);
            }
        }
    }

    float u[16];
    #pragma unroll
    for (int p = 0; p < 8; p++) upk2(u[2*p], u[2*p+1], U[p]);

    // segment transform V -> A16*V + bacc
    float bacc = 0.f;
    #pragma unroll
    for (int jj = 0; jj < 16; jj++) bacc = fmaf(ALPHA, bacc, u[jj]);

    // warp-inclusive scan of (a,b) composition
    float a = A16, bs = bacc;
    #pragma unroll
    for (int s = 1; s < 32; s <<= 1) {
        float ao = __shfl_up_sync(0xffffffffu, a, s);
        float bo = __shfl_up_sync(0xffffffffu, bs, s);
        if (lane >= s) { bs = fmaf(a, bo, bs); a *= ao; }
    }
    if (lane == 31) { swa[wrp] = a; swb[wrp] = bs; }
    __syncthreads();

    float pb = 0.f;
    for (int ww = 0; ww < wrp; ww++) pb = fmaf(swa[ww], pb, swb[ww]);

    float ae  = __shfl_up_sync(0xffffffffu, a, 1);
    float bse = __shfl_up_sync(0xffffffffu, bs, 1);
    if (lane == 0) { ae = 1.f; bse = 0.f; }
    float V = fmaf(ae, pb, bse);   // V at start of this thread's segment

    int ft = 0x7fffffff;
    #pragma unroll
    for (int jj = 0; jj < 16; jj++) {
        V = fmaf(ALPHA, V, u[jj]);
        if (V >= 1.0f && ft == 0x7fffffff) ft = t0 + jj;
    }
    if (ft != 0x7fffffff) atomicMin(&s_first, ft);
    __syncthreads();

    if (tid == 0) {
        float tl = (float)s_first;
        out[BC + bc] = tl;
        float scale = fmaxf(lat_scale[0], 0.001f);
        out[2 * BC + bc] = expf(-tl / scale);
    }
}

// ---------------- mix: warp-per-output, shuffle reduce ----------------
__global__ void __launch_bounds__(256) k_mix(const float* __restrict__ OG,
                                             const float* __restrict__ bias,
                                             const float* __restrict__ out_act) {
    __shared__ float sact[256];
    int b   = blockIdx.x >> 5;
    int ig0 = (blockIdx.x & 31) * 8;
    int lane = threadIdx.x & 31;
    int wrp  = threadIdx.x >> 5;
    sact[threadIdx.x] = out_act[b * CC + threadIdx.x];
    __syncthreads();

    int i = ig0 + wrp;
    float a = 0.f;
    #pragma unroll
    for (int kk = 0; kk < 8; kk++) {
        int j = lane + 32 * kk;
        a = fmaf(sact[j], OG[i * 256 + j], a);
    }
    #pragma unroll
    for (int s = 16; s > 0; s >>= 1) a += __shfl_xor_sync(0xffffffffu, a, s);
    if (lane == 0) g_mix[b * CC + i] = a + bias[i];
}

// ---------------- h partials: 4 j-chunks per batch row ----------------
__global__ void __launch_bounds__(128) k_h(const float* __restrict__ W1) {
    __shared__ float sm[64];
    int b  = blockIdx.x >> 2;
    int jc = blockIdx.x & 3;
    int i  = threadIdx.x;          // 0..127
    if (i < 64) sm[i] = g_mix[b * CC + jc * 64 + i];
    __syncthreads();

    float a0 = 0.f, a1 = 0.f, a2 = 0.f, a3 = 0.f;
    #pragma unroll
    for (int j = 0; j < 64; j += 4) {
        a0 = fmaf(sm[j    ], W1[(jc * 64 + j    ) * 128 + i], a0);
        a1 = fmaf(sm[j + 1], W1[(jc * 64 + j + 1) * 128 + i], a1);
        a2 = fmaf(sm[j + 2], W1[(jc * 64 + j + 2) * 128 + i], a2);
        a3 = fmaf(sm[j + 3], W1[(jc * 64 + j + 3) * 128 + i], a3);
    }
    g_hp[blockIdx.x * 128 + i] = (a0 + a1) + (a2 + a3);
}

// ---------------- reduce + pred ----------------
__global__ void __launch_bounds__(256) k_pred(const float* __restrict__ b1,
                                              const float* __restrict__ W2,
                                              const float* __restrict__ b2,
                                              float* __restrict__ out) {
    __shared__ float sh[128];
    int b = blockIdx.x, i = threadIdx.x;
    if (i < 128) {
        float s = b1[i];
        #pragma unroll
        for (int p = 0; p < 4; p++) s += g_hp[(b * 4 + p) * 128 + i];
        sh[i] = fmaxf(s, 0.f);
    }
    __syncthreads();

    float a0 = 0.f, a1 = 0.f, a2 = 0.f, a3 = 0.f;
    #pragma unroll
    for (int k = 0; k < 128; k += 4) {
        a0 = fmaf(sh[k    ], W2[(k    ) * 256 + i], a0);
        a1 = fmaf(sh[k + 1], W2[(k + 1) * 256 + i], a1);
        a2 = fmaf(sh[k + 2], W2[(k + 2) * 256 + i], a2);
        a3 = fmaf(sh[k + 3], W2[(k + 3) * 256 + i], a3);
    }
    float r = b2[i] + (a0 + a1) + (a2 + a3);
    float sp = (r > 20.f) ? r : log1pf(expf(r));
    out[b * CC + i] = fminf(sp, 4096.0f);
}

extern "C" void kernel_launch(void* const* d_in, const int* in_sizes, int n_in,
                              void* d_out, int out_size) {
    const float* x    = (const float*)d_in[0];
    const float* w3   = (const float*)d_in[1];
    const float* b3   = (const float*)d_in[2];
    const float* w5   = (const float*)d_in[3];
    const float* b5   = (const float*)d_in[4];
    const float* w9   = (const float*)d_in[5];
    const float* b9   = (const float*)d_in[6];
    const float* wred = (const float*)d_in[7];
    const float* bred = (const float*)d_in[8];
    const float* ls   = (const float*)d_in[9];
    const float* og   = (const float*)d_in[10];
    const float* bias = (const float*)d_in[11];
    const float* W1   = (const float*)d_in[12];
    const float* b1   = (const float*)d_in[13];
    const float* W2   = (const float*)d_in[14];
    const float* b2   = (const float*)d_in[15];
    float* out = (float*)d_out;

    size_t smem = (size_t)(3 * XSW) * sizeof(float);
    cudaFuncSetAttribute(lif_kernel, cudaFuncAttributeMaxDynamicSharedMemorySize, (int)smem);

    prep_kernel<<<3, 256>>>(w3, b3, w5, b5, w9, b9, wred, bred);
    lif_kernel<<<BC, 256, smem>>>(x, ls, out);
    k_mix<<<256, 256>>>(og, bias, out + 2 * BC);
    k_h<<<32, 128>>>(W1);
    k_pred<<<BB, 256>>>(b1, W2, b2, out);
}

// round 5
// speedup vs baseline: 1.9557x; 1.0833x over previous
#include <cuda_runtime.h>
#include <math.h>

#define CC 256
#define TT 4096
#define BB 8
#define BC (BB*CC)
#define ALPHA 0.8187307530779818f
#define ONE_M_ALPHA 0.1812692469220182f
#define A16 0.04076220397836621f   /* ALPHA^16 */

typedef unsigned long long ull;

// Effective-filter coefficients, duplicated-pair packed: (e,e) as f32x2, already * (1-alpha)
__device__ ull   g_E2[CC][3][9];
__device__ float g_beP[CC][3];     // bias partials * (1-alpha); m=0 slot includes bred

__device__ __forceinline__ ull pk2(float lo, float hi) {
    ull r; asm("mov.b64 %0, {%1, %2};" : "=l"(r) : "f"(lo), "f"(hi)); return r;
}
__device__ __forceinline__ void upk2(float& lo, float& hi, ull v) {
    asm("mov.b64 {%0, %1}, %2;" : "=f"(lo), "=f"(hi) : "l"(v));
}
__device__ __forceinline__ void fma2(ull& d, ull a, ull b) {
    asm("fma.rn.f32x2 %0, %1, %2, %0;" : "+l"(d) : "l"(a), "l"(b));
}

// ---------------- prep: thread = (c, m); 6 consecutive cat-channels each ----------------
__global__ void prep_kernel(const float* __restrict__ w3, const float* __restrict__ b3,
                            const float* __restrict__ w5, const float* __restrict__ b5,
                            const float* __restrict__ w9, const float* __restrict__ b9,
                            const float* __restrict__ wred, const float* __restrict__ bred) {
    int c = threadIdx.x;           // 0..255
    int m = blockIdx.x;            // 0..2
    int j0 = 18 * c + 6 * m;       // 6-aligned run, never straddles bucket boundary
    const float* w; const float* bb; int K, pc0;
    if (j0 < 6 * CC)       { w = w3; bb = b3; K = 3; pc0 = j0; }
    else if (j0 < 12 * CC) { w = w5; bb = b5; K = 5; pc0 = j0 - 6 * CC; }
    else                   { w = w9; bb = b9; K = 9; pc0 = j0 - 12 * CC; }
    int pad = (K - 1) / 2;

    float E[9];
    #pragma unroll
    for (int t = 0; t < 9; t++) E[t] = 0.f;
    float be = (m == 0) ? bred[c] : 0.f;

    for (int r = 0; r < 6; r++) {
        float wr = wred[c * 18 + 6 * m + r];
        be += wr * bb[pc0 + r];
        for (int u = 0; u < K; u++)
            E[4 + u - pad] += wr * w[(pc0 + r) * K + u];
    }
    #pragma unroll
    for (int t = 0; t < 9; t++) {
        float e = E[t] * ONE_M_ALPHA;
        g_E2[c][m][t] = pk2(e, e);
    }
    g_beP[c][m] = be * ONE_M_ALPHA;
}

// ---------------- lif: one block per (b, c); 16 timesteps/thread, no x staging ----------------
// out layout: [0,BC) pred (by k_tail), [BC,2BC) true_latency, [2BC,3BC) act.
__global__ void __launch_bounds__(256, 2) lif_kernel(const float* __restrict__ x,
                                                     const float* __restrict__ lat_scale,
                                                     float* __restrict__ out) {
    __shared__ ull sE2[27];
    __shared__ float swa[8], swb[8];
    __shared__ int s_first;

    int tid  = threadIdx.x;
    int lane = tid & 31;
    int wrp  = tid >> 5;
    int bc = blockIdx.x;
    int b  = bc >> 8;
    int c  = bc & 255;

    if (tid < 27) sE2[tid] = ((const ull*)g_E2)[c * 27 + tid];
    if (tid == 28) s_first = TT;
    __syncthreads();

    float be = g_beP[c][0] + g_beP[c][1] + g_beP[c][2];

    ull U[8];
    ull be2 = pk2(be, be);
    #pragma unroll
    for (int p = 0; p < 8; p++) U[p] = be2;

    #pragma unroll
    for (int m = 0; m < 3; m++) {
        int xch = (3 * c + m) & 255;
        const float4* row4 = (const float4*)(x + ((size_t)(b * CC + xch)) * TT);
        // core: w[4..19] = x[t0 .. t0+15]
        float4 c0 = row4[tid * 4 + 0];
        float4 c1 = row4[tid * 4 + 1];
        float4 c2 = row4[tid * 4 + 2];
        float4 c3 = row4[tid * 4 + 3];
        // halos via shuffle: prev thread's c3 -> w[0..3], next thread's c0 -> w[20..23]
        float4 hp, hn;
        hp.x = __shfl_up_sync(0xffffffffu, c3.x, 1);
        hp.y = __shfl_up_sync(0xffffffffu, c3.y, 1);
        hp.z = __shfl_up_sync(0xffffffffu, c3.z, 1);
        hp.w = __shfl_up_sync(0xffffffffu, c3.w, 1);
        hn.x = __shfl_down_sync(0xffffffffu, c0.x, 1);
        hn.y = __shfl_down_sync(0xffffffffu, c0.y, 1);
        hn.z = __shfl_down_sync(0xffffffffu, c0.z, 1);
        hn.w = __shfl_down_sync(0xffffffffu, c0.w, 1);
        if (lane == 0) {
            if (tid > 0) hp = row4[tid * 4 - 1];
            else         hp = make_float4(0.f, 0.f, 0.f, 0.f);
        }
        if (lane == 31) {
            if (tid < 255) hn = row4[tid * 4 + 4];
            else           hn = make_float4(0.f, 0.f, 0.f, 0.f);
        }

        float w[24];
        w[0]=hp.x; w[1]=hp.y; w[2]=hp.z; w[3]=hp.w;
        w[4]=c0.x; w[5]=c0.y; w[6]=c0.z; w[7]=c0.w;
        w[8]=c1.x; w[9]=c1.y; w[10]=c1.z; w[11]=c1.w;
        w[12]=c2.x; w[13]=c2.y; w[14]=c2.z; w[15]=c2.w;
        w[16]=c3.x; w[17]=c3.y; w[18]=c3.z; w[19]=c3.w;
        w[20]=hn.x; w[21]=hn.y; w[22]=hn.z; w[23]=hn.w;

        ull p0[12], p1[11];
        #pragma unroll
        for (int k = 0; k < 12; k++) p0[k] = pk2(w[2*k], w[2*k+1]);
        #pragma unroll
        for (int k = 0; k < 11; k++) p1[k] = pk2(w[2*k+1], w[2*k+2]);

        #pragma unroll
        for (int t = 0; t < 9; t++) {
            ull e2 = sE2[m * 9 + t];
            if ((t & 1) == 0) {
                #pragma unroll
                for (int p = 0; p < 8; p++) fma2(U[p], e2, p0[p + (t >> 1)]);
            } else {
                #pragma unroll
                for (int p = 0; p < 8; p++) fma2(U[p], e2, p1[p + (t >> 1)]);
            }
        }
    }

    float u[16];
    #pragma unroll
    for (int p = 0; p < 8; p++) upk2(u[2*p], u[2*p+1], U[p]);

    // segment transform V -> A16*V + bacc
    float bacc = 0.f;
    #pragma unroll
    for (int jj = 0; jj < 16; jj++) bacc = fmaf(ALPHA, bacc, u[jj]);

    // warp-inclusive scan of (a,b) composition
    float a = A16, bs = bacc;
    #pragma unroll
    for (int s = 1; s < 32; s <<= 1) {
        float ao = __shfl_up_sync(0xffffffffu, a, s);
        float bo = __shfl_up_sync(0xffffffffu, bs, s);
        if (lane >= s) { bs = fmaf(a, bo, bs); a *= ao; }
    }
    if (lane == 31) { swa[wrp] = a; swb[wrp] = bs; }
    __syncthreads();

    float pb = 0.f;
    for (int ww = 0; ww < wrp; ww++) pb = fmaf(swa[ww], pb, swb[ww]);

    float ae  = __shfl_up_sync(0xffffffffu, a, 1);
    float bse = __shfl_up_sync(0xffffffffu, bs, 1);
    if (lane == 0) { ae = 1.f; bse = 0.f; }
    float V = fmaf(ae, pb, bse);   // V at start of this thread's segment

    int t0 = tid * 16;
    int ft = 0x7fffffff;
    #pragma unroll
    for (int jj = 0; jj < 16; jj++) {
        V = fmaf(ALPHA, V, u[jj]);
        if (V >= 1.0f && ft == 0x7fffffff) ft = t0 + jj;
    }
    if (ft != 0x7fffffff) atomicMin(&s_first, ft);
    __syncthreads();

    if (tid == 0) {
        float tl = (float)s_first;
        out[BC + bc] = tl;
        float scale = fmaxf(lat_scale[0], 0.001f);
        out[2 * BC + bc] = expf(-tl / scale);
    }
}

// ---------------- fused tail: act -> mix -> h -> pred. One block per batch row ----------------
__global__ void __launch_bounds__(256) k_tail(const float* __restrict__ OG,
                                              const float* __restrict__ bias,
                                              const float* __restrict__ W1,
                                              const float* __restrict__ b1,
                                              const float* __restrict__ W2,
                                              const float* __restrict__ b2,
                                              float* __restrict__ out) {
    __shared__ float4 sact4[64];
    __shared__ float smix[256];
    __shared__ float sh[128];
    __shared__ float sp[1024];      // reused: [8][128] for h, [4][256] for pred

    int b = blockIdx.x;
    int t = threadIdx.x;
    int lane = t & 31;
    int wrp  = t >> 5;

    if (t < 64) sact4[t] = ((const float4*)(out + 2 * BC + b * CC))[t];
    __syncthreads();

    // ---- mix: warp per 32 outputs, coalesced float4 OG rows, shfl reduce ----
    const float4* OG4 = (const float4*)OG;
    #pragma unroll 4
    for (int oo = 0; oo < 32; oo++) {
        int i = wrp * 32 + oo;
        float4 g0 = OG4[i * 64 + lane];
        float4 g1 = OG4[i * 64 + 32 + lane];
        float4 a0 = sact4[lane];
        float4 a1 = sact4[32 + lane];
        float acc = g0.x * a0.x;
        acc = fmaf(g0.y, a0.y, acc);
        acc = fmaf(g0.z, a0.z, acc);
        acc = fmaf(g0.w, a0.w, acc);
        acc = fmaf(g1.x, a1.x, acc);
        acc = fmaf(g1.y, a1.y, acc);
        acc = fmaf(g1.z, a1.z, acc);
        acc = fmaf(g1.w, a1.w, acc);
        #pragma unroll
        for (int s = 16; s > 0; s >>= 1) acc += __shfl_xor_sync(0xffffffffu, acc, s);
        if (lane == 0) smix[i] = acc + bias[i];
    }
    __syncthreads();

    // ---- h: thread -> 4 outputs (i4 = (t&31)*4), j-chunk = t>>5 (8 chunks of 32) ----
    {
        const float4* W14 = (const float4*)W1;
        int il = t & 31;
        int ch = t >> 5;
        float4 acc = make_float4(0.f, 0.f, 0.f, 0.f);
        #pragma unroll 8
        for (int jj = 0; jj < 32; jj++) {
            int j = ch * 32 + jj;
            float mj = smix[j];
            float4 wr = W14[j * 32 + il];
            acc.x = fmaf(mj, wr.x, acc.x);
            acc.y = fmaf(mj, wr.y, acc.y);
            acc.z = fmaf(mj, wr.z, acc.z);
            acc.w = fmaf(mj, wr.w, acc.w);
        }
        ((float4*)sp)[ch * 32 + il] = acc;
    }
    __syncthreads();
    if (t < 128) {
        float s = b1[t];
        #pragma unroll
        for (int ch = 0; ch < 8; ch++) s += sp[ch * 128 + t];
        sh[t] = fmaxf(s, 0.f);
    }
    __syncthreads();

    // ---- pred: thread -> 4 outputs (i4 = (t&63)*4), k-chunk = t>>6 (4 chunks of 32) ----
    {
        const float4* W24 = (const float4*)W2;
        int il = t & 63;
        int ch = t >> 6;
        float4 acc = make_float4(0.f, 0.f, 0.f, 0.f);
        #pragma unroll 8
        for (int kk = 0; kk < 32; kk++) {
            int k = ch * 32 + kk;
            float hk = sh[k];
            float4 wr = W24[k * 64 + il];
            acc.x = fmaf(hk, wr.x, acc.x);
            acc.y = fmaf(hk, wr.y, acc.y);
            acc.z = fmaf(hk, wr.z, acc.z);
            acc.w = fmaf(hk, wr.w, acc.w);
        }
        ((float4*)sp)[ch * 64 + il] = acc;
    }
    __syncthreads();
    {
        float r = b2[t];
        #pragma unroll
        for (int ch = 0; ch < 4; ch++) r += sp[ch * 256 + t];
        float spv = (r > 20.f) ? r : log1pf(expf(r));
        out[b * CC + t] = fminf(spv, 4096.0f);
    }
}

extern "C" void kernel_launch(void* const* d_in, const int* in_sizes, int n_in,
                              void* d_out, int out_size) {
    const float* x    = (const float*)d_in[0];
    const float* w3   = (const float*)d_in[1];
    const float* b3   = (const float*)d_in[2];
    const float* w5   = (const float*)d_in[3];
    const float* b5   = (const float*)d_in[4];
    const float* w9   = (const float*)d_in[5];
    const float* b9   = (const float*)d_in[6];
    const float* wred = (const float*)d_in[7];
    const float* bred = (const float*)d_in[8];
    const float* ls   = (const float*)d_in[9];
    const float* og   = (const float*)d_in[10];
    const float* bias = (const float*)d_in[11];
    const float* W1   = (const float*)d_in[12];
    const float* b1   = (const float*)d_in[13];
    const float* W2   = (const float*)d_in[14];
    const float* b2   = (const float*)d_in[15];
    float* out = (float*)d_out;

    prep_kernel<<<3, 256>>>(w3, b3, w5, b5, w9, b9, wred, bred);
    lif_kernel<<<BC, 256>>>(x, ls, out);
    k_tail<<<BB, 256>>>(og, bias, W1, b1, W2, b2, out);
}

// round 6
// speedup vs baseline: 2.3584x; 1.2059x over previous
#include <cuda_runtime.h>
#include <math.h>

#define CC 256
#define TT 4096
#define BB 8
#define BC (BB*CC)
#define ALPHA 0.8187307530779818f
#define ONE_M_ALPHA 0.1812692469220182f
#define A8 0.20189651799465540f   /* ALPHA^8 = exp(-1.6) */

typedef unsigned long long ull;

// Effective-filter coefficients, duplicated-pair packed: (e,e) as f32x2, already * (1-alpha)
__device__ ull   g_E2[CC][3][9];
__device__ float g_beP[CC][3];     // bias partials * (1-alpha); m=0 slot includes bred

__device__ __forceinline__ ull pk2(float lo, float hi) {
    ull r; asm("mov.b64 %0, {%1, %2};" : "=l"(r) : "f"(lo), "f"(hi)); return r;
}
__device__ __forceinline__ void upk2(float& lo, float& hi, ull v) {
    asm("mov.b64 {%0, %1}, %2;" : "=f"(lo), "=f"(hi) : "l"(v));
}
__device__ __forceinline__ void fma2(ull& d, ull a, ull b) {
    asm("fma.rn.f32x2 %0, %1, %2, %0;" : "+l"(d) : "l"(a), "l"(b));
}

// ---------------- prep: 8 lanes per (c,m) pair; shfl-tree reduction ----------------
// grid 24 x 256: pair index pg = c*3+m, lanes sub=0..7 handle reduce-rows r=sub (<6).
__global__ void __launch_bounds__(256) prep_kernel(
        const float* __restrict__ w3, const float* __restrict__ b3,
        const float* __restrict__ w5, const float* __restrict__ b5,
        const float* __restrict__ w9, const float* __restrict__ b9,
        const float* __restrict__ wred, const float* __restrict__ bred) {
    int tid = blockIdx.x * 256 + threadIdx.x;
    int pg  = tid >> 3;            // 0..767
    int sub = tid & 7;
    if (pg >= 3 * CC) return;
    int c = pg / 3;
    int m = pg - 3 * c;
    int j0 = 18 * c + 6 * m;
    const float* w; const float* bb; int K, pc0;
    if (j0 < 6 * CC)       { w = w3; bb = b3; K = 3; pc0 = j0; }
    else if (j0 < 12 * CC) { w = w5; bb = b5; K = 5; pc0 = j0 - 6 * CC; }
    else                   { w = w9; bb = b9; K = 9; pc0 = j0 - 12 * CC; }
    int pad = (K - 1) / 2;

    float E[9];
    #pragma unroll
    for (int t = 0; t < 9; t++) E[t] = 0.f;
    float be = 0.f;

    if (sub < 6) {
        int r = sub;
        float wr = wred[c * 18 + 6 * m + r];
        be = wr * bb[pc0 + r];
        for (int u = 0; u < K; u++)
            E[4 + u - pad] = wr * w[(pc0 + r) * K + u];
    }
    // reduce across the 8-lane group (xor 1,2,4 stays in group)
    #pragma unroll
    for (int s = 4; s > 0; s >>= 1) {
        #pragma unroll
        for (int t = 0; t < 9; t++) E[t] += __shfl_xor_sync(0xffffffffu, E[t], s);
        be += __shfl_xor_sync(0xffffffffu, be, s);
    }
    if (sub == 0) {
        #pragma unroll
        for (int t = 0; t < 9; t++) {
            float e = E[t] * ONE_M_ALPHA;
            g_E2[c][m][t] = pk2(e, e);
        }
        g_beP[c][m] = be * ONE_M_ALPHA + ((m == 0) ? bred[c] * ONE_M_ALPHA : 0.f);
    }
}

// ---------------- lif: one block per (b, c); 512 threads, 8 timesteps/thread ----------------
// out layout: [0,BC) pred (by k_tail), [BC,2BC) true_latency, [2BC,3BC) act.
__global__ void __launch_bounds__(512, 2) lif_kernel(const float* __restrict__ x,
                                                     const float* __restrict__ lat_scale,
                                                     float* __restrict__ out) {
    __shared__ ull sE2[27];
    __shared__ float swa[16], swb[16];
    __shared__ int s_first;

    int tid  = threadIdx.x;
    int lane = tid & 31;
    int wrp  = tid >> 5;
    int bc = blockIdx.x;
    int b  = bc >> 8;
    int c  = bc & 255;

    if (tid < 27) sE2[tid] = ((const ull*)g_E2)[c * 27 + tid];
    if (tid == 28) s_first = TT;
    __syncthreads();

    float be = g_beP[c][0] + g_beP[c][1] + g_beP[c][2];

    ull U[4];
    ull be2 = pk2(be, be);
    #pragma unroll
    for (int p = 0; p < 4; p++) U[p] = be2;

    #pragma unroll
    for (int m = 0; m < 3; m++) {
        int xch = (3 * c + m) & 255;
        const float4* row4 = (const float4*)(x + ((size_t)(b * CC + xch)) * TT);
        // core: w[4..11] = x[t0 .. t0+7]
        float4 c0 = row4[tid * 2 + 0];
        float4 c1 = row4[tid * 2 + 1];
        // halos: prev thread's c1 -> w[0..3], next thread's c0 -> w[12..15]
        float4 hp, hn;
        hp.x = __shfl_up_sync(0xffffffffu, c1.x, 1);
        hp.y = __shfl_up_sync(0xffffffffu, c1.y, 1);
        hp.z = __shfl_up_sync(0xffffffffu, c1.z, 1);
        hp.w = __shfl_up_sync(0xffffffffu, c1.w, 1);
        hn.x = __shfl_down_sync(0xffffffffu, c0.x, 1);
        hn.y = __shfl_down_sync(0xffffffffu, c0.y, 1);
        hn.z = __shfl_down_sync(0xffffffffu, c0.z, 1);
        hn.w = __shfl_down_sync(0xffffffffu, c0.w, 1);
        if (lane == 0) {
            if (tid > 0) hp = row4[tid * 2 - 1];
            else         hp = make_float4(0.f, 0.f, 0.f, 0.f);
        }
        if (lane == 31) {
            if (tid < 511) hn = row4[tid * 2 + 2];
            else           hn = make_float4(0.f, 0.f, 0.f, 0.f);
        }

        float w[16];
        w[0]=hp.x;  w[1]=hp.y;  w[2]=hp.z;  w[3]=hp.w;
        w[4]=c0.x;  w[5]=c0.y;  w[6]=c0.z;  w[7]=c0.w;
        w[8]=c1.x;  w[9]=c1.y;  w[10]=c1.z; w[11]=c1.w;
        w[12]=hn.x; w[13]=hn.y; w[14]=hn.z; w[15]=hn.w;

        ull p0[8], p1[7];
        #pragma unroll
        for (int k = 0; k < 8; k++) p0[k] = pk2(w[2*k], w[2*k+1]);
        #pragma unroll
        for (int k = 0; k < 7; k++) p1[k] = pk2(w[2*k+1], w[2*k+2]);

        #pragma unroll
        for (int t = 0; t < 9; t++) {
            ull e2 = sE2[m * 9 + t];
            if ((t & 1) == 0) {
                #pragma unroll
                for (int p = 0; p < 4; p++) fma2(U[p], e2, p0[p + (t >> 1)]);
            } else {
                #pragma unroll
                for (int p = 0; p < 4; p++) fma2(U[p], e2, p1[p + (t >> 1)]);
            }
        }
    }

    float u[8];
    #pragma unroll
    for (int p = 0; p < 4; p++) upk2(u[2*p], u[2*p+1], U[p]);

    // segment transform V -> A8*V + bacc
    float bacc = 0.f;
    #pragma unroll
    for (int jj = 0; jj < 8; jj++) bacc = fmaf(ALPHA, bacc, u[jj]);

    // warp-inclusive scan of (a,b) composition
    float a = A8, bs = bacc;
    #pragma unroll
    for (int s = 1; s < 32; s <<= 1) {
        float ao = __shfl_up_sync(0xffffffffu, a, s);
        float bo = __shfl_up_sync(0xffffffffu, bs, s);
        if (lane >= s) { bs = fmaf(a, bo, bs); a *= ao; }
    }
    if (lane == 31) { swa[wrp] = a; swb[wrp] = bs; }
    __syncthreads();

    float pb = 0.f;
    for (int ww = 0; ww < wrp; ww++) pb = fmaf(swa[ww], pb, swb[ww]);

    float ae  = __shfl_up_sync(0xffffffffu, a, 1);
    float bse = __shfl_up_sync(0xffffffffu, bs, 1);
    if (lane == 0) { ae = 1.f; bse = 0.f; }
    float V = fmaf(ae, pb, bse);   // V at start of this thread's segment

    int t0 = tid * 8;
    int ft = 0x7fffffff;
    #pragma unroll
    for (int jj = 0; jj < 8; jj++) {
        V = fmaf(ALPHA, V, u[jj]);
        if (V >= 1.0f && ft == 0x7fffffff) ft = t0 + jj;
    }
    if (ft != 0x7fffffff) atomicMin(&s_first, ft);
    __syncthreads();

    if (tid == 0) {
        float tl = (float)s_first;
        out[BC + bc] = tl;
        float scale = fmaxf(lat_scale[0], 0.001f);
        out[2 * BC + bc] = expf(-tl / scale);
    }
}

// ---------------- fused tail: act -> mix -> h -> pred. One block per batch row ----------------
__global__ void __launch_bounds__(256) k_tail(const float* __restrict__ OG,
                                              const float* __restrict__ bias,
                                              const float* __restrict__ W1,
                                              const float* __restrict__ b1,
                                              const float* __restrict__ W2,
                                              const float* __restrict__ b2,
                                              float* __restrict__ out) {
    __shared__ float4 sact4[64];
    __shared__ float smix[256];
    __shared__ float sh[128];
    __shared__ float sp[1024];      // reused: [8][128] for h, [4][256] for pred

    int b = blockIdx.x;
    int t = threadIdx.x;
    int lane = t & 31;
    int wrp  = t >> 5;

    if (t < 64) sact4[t] = ((const float4*)(out + 2 * BC + b * CC))[t];
    __syncthreads();

    // ---- mix: warp per 32 outputs, coalesced float4 OG rows, shfl reduce ----
    const float4* OG4 = (const float4*)OG;
    #pragma unroll 4
    for (int oo = 0; oo < 32; oo++) {
        int i = wrp * 32 + oo;
        float4 g0 = OG4[i * 64 + lane];
        float4 g1 = OG4[i * 64 + 32 + lane];
        float4 a0 = sact4[lane];
        float4 a1 = sact4[32 + lane];
        float acc = g0.x * a0.x;
        acc = fmaf(g0.y, a0.y, acc);
        acc = fmaf(g0.z, a0.z, acc);
        acc = fmaf(g0.w, a0.w, acc);
        acc = fmaf(g1.x, a1.x, acc);
        acc = fmaf(g1.y, a1.y, acc);
        acc = fmaf(g1.z, a1.z, acc);
        acc = fmaf(g1.w, a1.w, acc);
        #pragma unroll
        for (int s = 16; s > 0; s >>= 1) acc += __shfl_xor_sync(0xffffffffu, acc, s);
        if (lane == 0) smix[i] = acc + bias[i];
    }
    __syncthreads();

    // ---- h: thread -> 4 outputs, j-chunk = t>>5 (8 chunks of 32) ----
    {
        const float4* W14 = (const float4*)W1;
        int il = t & 31;
        int ch = t >> 5;
        float4 acc = make_float4(0.f, 0.f, 0.f, 0.f);
        #pragma unroll 8
        for (int jj = 0; jj < 32; jj++) {
            int j = ch * 32 + jj;
            float mj = smix[j];
            float4 wr = W14[j * 32 + il];
            acc.x = fmaf(mj, wr.x, acc.x);
            acc.y = fmaf(mj, wr.y, acc.y);
            acc.z = fmaf(mj, wr.z, acc.z);
            acc.w = fmaf(mj, wr.w, acc.w);
        }
        ((float4*)sp)[ch * 32 + il] = acc;
    }
    __syncthreads();
    if (t < 128) {
        float s = b1[t];
        #pragma unroll
        for (int ch = 0; ch < 8; ch++) s += sp[ch * 128 + t];
        sh[t] = fmaxf(s, 0.f);
    }
    __syncthreads();

    // ---- pred: thread -> 4 outputs, k-chunk = t>>6 (4 chunks of 32) ----
    {
        const float4* W24 = (const float4*)W2;
        int il = t & 63;
        int ch = t >> 6;
        float4 acc = make_float4(0.f, 0.f, 0.f, 0.f);
        #pragma unroll 8
        for (int kk = 0; kk < 32; kk++) {
            int k = ch * 32 + kk;
            float hk = sh[k];
            float4 wr = W24[k * 64 + il];
            acc.x = fmaf(hk, wr.x, acc.x);
            acc.y = fmaf(hk, wr.y, acc.y);
            acc.z = fmaf(hk, wr.z, acc.z);
            acc.w = fmaf(hk, wr.w, acc.w);
        }
        ((float4*)sp)[ch * 64 + il] = acc;
    }
    __syncthreads();
    {
        float r = b2[t];
        #pragma unroll
        for (int ch = 0; ch < 4; ch++) r += sp[ch * 256 + t];
        float spv = (r > 20.f) ? r : log1pf(expf(r));
        out[b * CC + t] = fminf(spv, 4096.0f);
    }
}

extern "C" void kernel_launch(void* const* d_in, const int* in_sizes, int n_in,
                              void* d_out, int out_size) {
    const float* x    = (const float*)d_in[0];
    const float* w3   = (const float*)d_in[1];
    const float* b3   = (const float*)d_in[2];
    const float* w5   = (const float*)d_in[3];
    const float* b5   = (const float*)d_in[4];
    const float* w9   = (const float*)d_in[5];
    const float* b9   = (const float*)d_in[6];
    const float* wred = (const float*)d_in[7];
    const float* bred = (const float*)d_in[8];
    const float* ls   = (const float*)d_in[9];
    const float* og   = (const float*)d_in[10];
    const float* bias = (const float*)d_in[11];
    const float* W1   = (const float*)d_in[12];
    const float* b1   = (const float*)d_in[13];
    const float* W2   = (const float*)d_in[14];
    const float* b2   = (const float*)d_in[15];
    float* out = (float*)d_out;

    prep_kernel<<<24, 256>>>(w3, b3, w5, b5, w9, b9, wred, bred);
    lif_kernel<<<BC, 512>>>(x, ls, out);
    k_tail<<<BB, 256>>>(og, bias, W1, b1, W2, b2, out);
}